// round 14
// baseline (speedup 1.0000x reference)
#include <cuda_runtime.h>
#include <cstdint>
#include <cstddef>

#define B_TOTAL 65536
#define NGRAPH  64
#define NNODES  2048
#define NEDGES  16384
#define META    64
#define TXD     8
#define NOISE   128
#define RROWS   32    // rows per block in main kernel
#define NFEAT   41
#define SPAD    36
#define ESPLIT  8
#define GK      128   // gcn_gemm K-splits
#define GROWS   16    // rows per gcn_gemm block

typedef unsigned long long ull;

// Scratch: [deg_part | agg_part | g_go]; partials are [g][sp][node]
#define PART_FLOATS (NGRAPH * ESPLIT * NNODES)          // 1048576
#define SCRATCH_FLOATS (2 * PART_FLOATS + NGRAPH * NOISE)
__device__ float scratch[SCRATCH_FLOATS];
#define DEG_PART (scratch)
#define AGG_PART (scratch + PART_FLOATS)
#define G_GO     (scratch + 2 * PART_FLOATS)

// ---------- PDL ----------
__device__ __forceinline__ void pdl_wait() {
    asm volatile("griddepcontrol.wait;" ::: "memory");
}

// ---------- f32x2 helpers ----------
__device__ __forceinline__ ull pack2(float lo, float hi) {
    ull r; asm("mov.b64 %0, {%1,%2};" : "=l"(r) : "f"(lo), "f"(hi)); return r;
}
__device__ __forceinline__ ull fma2(ull a, ull b, ull c) {
    ull d; asm("fma.rn.f32x2 %0, %1, %2, %3;" : "=l"(d) : "l"(a), "l"(b), "l"(c)); return d;
}
__device__ __forceinline__ void unpack2(ull v, float& lo, float& hi) {
    asm("mov.b64 {%0,%1}, %2;" : "=f"(lo), "=f"(hi) : "l"(v));
}
__device__ __forceinline__ void stcs4(float* p, float4 v) {
    asm volatile("st.global.cs.v4.f32 [%0], {%1,%2,%3,%4};"
                 :: "l"(p), "f"(v.x), "f"(v.y), "f"(v.z), "f"(v.w) : "memory");
}

// ============================================================================
// k_deg (chain head, no wait): per-split smem edge count -> dense STG of
// deg_part. Split-0 blocks also zero g_go (consumed 2 grids later).
// ============================================================================
__global__ __launch_bounds__(256) void k_deg(const int* __restrict__ edges) {
    __shared__ int cnt[NNODES];
    const int g  = blockIdx.x >> 3;
    const int sp = blockIdx.x & 7;
    const int tid = threadIdx.x;

    const int4* dst4 = reinterpret_cast<const int4*>(
        edges + (size_t)g * 2 * NEDGES + NEDGES) + sp * (NEDGES / ESPLIT / 4);
    int4 d0 = __ldg(&dst4[tid]);
    int4 d1 = __ldg(&dst4[256 + tid]);

    if (sp == 0 && tid < NOISE) G_GO[g * NOISE + tid] = 0.f;

    #pragma unroll
    for (int i = 0; i < NNODES / 256; i++) cnt[i * 256 + tid] = 0;
    __syncthreads();

    atomicAdd(&cnt[d0.x], 1);
    atomicAdd(&cnt[d0.y], 1);
    atomicAdd(&cnt[d0.z], 1);
    atomicAdd(&cnt[d0.w], 1);
    atomicAdd(&cnt[d1.x], 1);
    atomicAdd(&cnt[d1.y], 1);
    atomicAdd(&cnt[d1.z], 1);
    atomicAdd(&cnt[d1.w], 1);
    __syncthreads();

    float* op = DEG_PART + (size_t)blockIdx.x * NNODES;
    #pragma unroll
    for (int i = 0; i < NNODES / 256; i++)
        op[i * 256 + tid] = (float)cnt[i * 256 + tid];
}

// ============================================================================
// k_norm: edge loads (prologue) -> wait -> sum deg partials -> dinv in smem ->
// smem-accumulate split's norm contributions -> dense STG of agg_part.
// ============================================================================
__global__ __launch_bounds__(256) void k_norm(const int* __restrict__ edges) {
    __shared__ float dinv_s[NNODES];
    __shared__ float agg_s[NNODES];
    const int g  = blockIdx.x >> 3;
    const int sp = blockIdx.x & 7;
    const int tid = threadIdx.x;

    const int* base = edges + (size_t)g * 2 * NEDGES;
    const int4* src4 = reinterpret_cast<const int4*>(base) + sp * (NEDGES / ESPLIT / 4);
    const int4* dst4 = reinterpret_cast<const int4*>(base + NEDGES) + sp * (NEDGES / ESPLIT / 4);
    int4 s0 = __ldg(&src4[tid]);
    int4 s1 = __ldg(&src4[256 + tid]);
    int4 d0 = __ldg(&dst4[tid]);
    int4 d1 = __ldg(&dst4[256 + tid]);

    pdl_wait();   // deg_part complete

    const float* dp = DEG_PART + (size_t)g * ESPLIT * NNODES;
    #pragma unroll
    for (int i = 0; i < NNODES / 256; i++) {
        int n = i * 256 + tid;
        float s = 1.0f;   // self loop
        #pragma unroll
        for (int spp = 0; spp < ESPLIT; spp++)
            s += __ldg(&dp[spp * NNODES + n]);
        dinv_s[n] = rsqrtf(s);
        agg_s[n]  = 0.f;
    }
    __syncthreads();

    atomicAdd(&agg_s[d0.x], dinv_s[s0.x] * dinv_s[d0.x]);
    atomicAdd(&agg_s[d0.y], dinv_s[s0.y] * dinv_s[d0.y]);
    atomicAdd(&agg_s[d0.z], dinv_s[s0.z] * dinv_s[d0.z]);
    atomicAdd(&agg_s[d0.w], dinv_s[s0.w] * dinv_s[d0.w]);
    atomicAdd(&agg_s[d1.x], dinv_s[s1.x] * dinv_s[d1.x]);
    atomicAdd(&agg_s[d1.y], dinv_s[s1.y] * dinv_s[d1.y]);
    atomicAdd(&agg_s[d1.z], dinv_s[s1.z] * dinv_s[d1.z]);
    atomicAdd(&agg_s[d1.w], dinv_s[s1.w] * dinv_s[d1.w]);
    __syncthreads();

    float* op = AGG_PART + (size_t)blockIdx.x * NNODES;
    #pragma unroll
    for (int i = 0; i < NNODES / 256; i++)
        op[i * 256 + tid] = agg_s[i * 256 + tid];
}

// ============================================================================
// gcn_gemm: 1024 blocks = 128 K-splits (16 rows) x 8 graph-groups.
// Pass A (pre-wait): wsum. Wait. Sum partials -> agg+dinv^2 -> 16x8 FMA.
// ============================================================================
__global__ __launch_bounds__(128) void gcn_gemm(
    const float* __restrict__ embW, const float* __restrict__ gwp,
    const float* __restrict__ gbp)
{
    __shared__ float aggs[8][GROWS];
    const int tid = threadIdx.x;
    const int ks  = blockIdx.x & (GK - 1);
    const int gsp = blockIdx.x >> 7;

    const float* wb = embW + (size_t)ks * GROWS * NOISE + tid;
    float wsum = 0.f;
    #pragma unroll
    for (int n = 0; n < GROWS; n++)
        wsum += __ldg(wb + (size_t)n * NOISE);

    pdl_wait();   // agg_part complete

    {
        int j = tid >> 4, n = tid & (GROWS - 1);
        int g = gsp * 8 + j;
        int node = ks * GROWS + n;
        const float* dp = DEG_PART + (size_t)g * ESPLIT * NNODES + node;
        const float* ap = AGG_PART + (size_t)g * ESPLIT * NNODES + node;
        float dsum = 1.0f, asum = 0.f;
        #pragma unroll
        for (int sp = 0; sp < ESPLIT; sp++) {
            dsum += __ldg(&dp[sp * NNODES]);
            asum += __ldg(&ap[sp * NNODES]);
        }
        float r = rsqrtf(dsum);
        aggs[j][n] = asum + r * r;
    }
    __syncthreads();

    float acc[8] = {0.f, 0.f, 0.f, 0.f, 0.f, 0.f, 0.f, 0.f};
    #pragma unroll
    for (int n = 0; n < GROWS; n++) {
        float wv = __ldg(wb + (size_t)n * NOISE);
        #pragma unroll
        for (int j = 0; j < 8; j++)
            acc[j] = fmaf(aggs[j][n], wv, acc[j]);
    }
    const float w = gwp[0], b = gbp[0];
    const float bterm = b * wsum;
    #pragma unroll
    for (int j = 0; j < 8; j++)
        atomicAdd(&G_GO[(gsp * 8 + j) * NOISE + tid], fmaf(w, acc[j], bterm));
}

// ============================================================================
// noise_main (R12 layout): staging + trig MLP PRE-wait; wait; g_go gather
// fused into acc init; f32x2 output GEMM. 128 threads, 32 rows, 7 blocks/SM.
// ============================================================================
__global__ __launch_bounds__(128, 7) void noise_main(
    const int*   __restrict__ gid,   const float* __restrict__ chain,
    const float* __restrict__ td,    const float* __restrict__ tx,
    const float* __restrict__ trigW, const float* __restrict__ trigb,
    const float* __restrict__ embW,  const float* __restrict__ embb,
    float* __restrict__ out)
{
    __shared__ __align__(16) float td_s[META][SPAD];
    __shared__ __align__(16) float feat_s[NFEAT][SPAD];
    __shared__ int gs[RROWS];

    const int tid = threadIdx.x;
    const int r0  = blockIdx.x * RROWS;
    const int lane = tid & 31;
    const int w    = tid >> 5;

    {
        const float4* tdg = reinterpret_cast<const float4*>(td + (size_t)r0 * META);
        #pragma unroll
        for (int it = 0; it < 4; it++) {
            int i = it * 128 + tid;
            int r = i >> 4;
            int q = i & 15;
            float4 v = tdg[i];
            float vv[4] = {v.x, v.y, v.z, v.w};
            #pragma unroll
            for (int j = 0; j < 4; j++) {
                int c = ((q >> 1) + j) & 3;
                td_s[4 * q + c][r] = vv[c];
            }
        }
        if (tid < 64) {
            const float4* txg = reinterpret_cast<const float4*>(tx + (size_t)r0 * TXD);
            int r = tid >> 1, q = tid & 1;
            float4 v = txg[tid];
            feat_s[33 + 4 * q + 0][r] = v.x;
            feat_s[33 + 4 * q + 1][r] = v.y;
            feat_s[33 + 4 * q + 2][r] = v.z;
            feat_s[33 + 4 * q + 3][r] = v.w;
        }
        if (tid < RROWS) {
            feat_s[0][tid] = chain[r0 + tid];
            gs[tid] = gid[r0 + tid];
        }
    }
    __syncthreads();

    {
        const int k = lane;
        float tb = __ldg(&trigb[k]);
        ull acc0 = pack2(tb, tb), acc1 = acc0, acc2 = acc0, acc3 = acc0;
        #pragma unroll 8
        for (int m = 0; m < META; m++) {
            float wv = __ldg(&trigW[m * 32 + k]);
            ull wd = pack2(wv, wv);
            ulonglong2 t01 = *reinterpret_cast<const ulonglong2*>(&td_s[m][8 * w]);
            ulonglong2 t23 = *reinterpret_cast<const ulonglong2*>(&td_s[m][8 * w + 4]);
            acc0 = fma2(wd, t01.x, acc0);
            acc1 = fma2(wd, t01.y, acc1);
            acc2 = fma2(wd, t23.x, acc2);
            acc3 = fma2(wd, t23.y, acc3);
        }
        float a, b2;
        unpack2(acc0, a, b2);
        *reinterpret_cast<ull*>(&feat_s[1 + k][8 * w + 0]) = pack2(fmaxf(a, 0.f), fmaxf(b2, 0.f));
        unpack2(acc1, a, b2);
        *reinterpret_cast<ull*>(&feat_s[1 + k][8 * w + 2]) = pack2(fmaxf(a, 0.f), fmaxf(b2, 0.f));
        unpack2(acc2, a, b2);
        *reinterpret_cast<ull*>(&feat_s[1 + k][8 * w + 4]) = pack2(fmaxf(a, 0.f), fmaxf(b2, 0.f));
        unpack2(acc3, a, b2);
        *reinterpret_cast<ull*>(&feat_s[1 + k][8 * w + 6]) = pack2(fmaxf(a, 0.f), fmaxf(b2, 0.f));
    }
    __syncthreads();

    pdl_wait();   // g_go complete

    {
        const int jq = lane;
        const float4 eb = __ldg(reinterpret_cast<const float4*>(&embb[4 * jq]));

        ull acc[4][4];
        #pragma unroll
        for (int u = 0; u < 4; u++) {
            int ra = 8 * w + 2 * u, rb = ra + 1;
            float4 ga = __ldg(reinterpret_cast<const float4*>(&G_GO[gs[ra] * NOISE + 4 * jq]));
            float4 gb = __ldg(reinterpret_cast<const float4*>(&G_GO[gs[rb] * NOISE + 4 * jq]));
            acc[u][0] = pack2(ga.x + eb.x, gb.x + eb.x);
            acc[u][1] = pack2(ga.y + eb.y, gb.y + eb.y);
            acc[u][2] = pack2(ga.z + eb.z, gb.z + eb.z);
            acc[u][3] = pack2(ga.w + eb.w, gb.w + eb.w);
        }

        const float4* wrow = reinterpret_cast<const float4*>(embW + (size_t)2048 * NOISE) + jq;
        #pragma unroll 4
        for (int k = 0; k < NFEAT; k++) {
            float4 wv = __ldg(wrow + (size_t)k * (NOISE / 4));
            ull wd0 = pack2(wv.x, wv.x);
            ull wd1 = pack2(wv.y, wv.y);
            ull wd2 = pack2(wv.z, wv.z);
            ull wd3 = pack2(wv.w, wv.w);
            ulonglong2 t01 = *reinterpret_cast<const ulonglong2*>(&feat_s[k][8 * w]);
            ulonglong2 t23 = *reinterpret_cast<const ulonglong2*>(&feat_s[k][8 * w + 4]);
            ull tp[4] = {t01.x, t01.y, t23.x, t23.y};
            #pragma unroll
            for (int u = 0; u < 4; u++) {
                acc[u][0] = fma2(wd0, tp[u], acc[u][0]);
                acc[u][1] = fma2(wd1, tp[u], acc[u][1]);
                acc[u][2] = fma2(wd2, tp[u], acc[u][2]);
                acc[u][3] = fma2(wd3, tp[u], acc[u][3]);
            }
        }

        #pragma unroll
        for (int u = 0; u < 4; u++) {
            size_t ra = (size_t)(r0 + 8 * w + 2 * u);
            float4 lo, hi;
            unpack2(acc[u][0], lo.x, hi.x);
            unpack2(acc[u][1], lo.y, hi.y);
            unpack2(acc[u][2], lo.z, hi.z);
            unpack2(acc[u][3], lo.w, hi.w);
            stcs4(out + ra * NOISE + 4 * jq, lo);
            stcs4(out + (ra + 1) * NOISE + 4 * jq, hi);
        }
    }
}

// ============================================================================
extern "C" void kernel_launch(void* const* d_in, const int* in_sizes, int n_in,
                              void* d_out, int out_size) {
    (void)in_sizes; (void)n_in; (void)out_size;
    const int*   gid   = (const int*)  d_in[0];
    const float* chain = (const float*)d_in[1];
    const float* td    = (const float*)d_in[2];
    const float* tx    = (const float*)d_in[3];
    const int*   edges = (const int*)  d_in[4];
    const float* gw    = (const float*)d_in[5];
    const float* gb    = (const float*)d_in[6];
    const float* trigW = (const float*)d_in[7];
    const float* trigb = (const float*)d_in[8];
    const float* embW  = (const float*)d_in[9];
    const float* embb  = (const float*)d_in[10];
    float* out = (float*)d_out;

    cudaLaunchAttribute pattr;
    pattr.id = cudaLaunchAttributeProgrammaticStreamSerialization;
    pattr.val.programmaticStreamSerializationAllowed = 1;

    // chain head: plain launch, no wait inside
    k_deg<<<NGRAPH * ESPLIT, 256>>>(edges);

    cudaLaunchConfig_t cfg = {};
    cfg.blockDim = dim3(256, 1, 1);
    cfg.stream   = 0;
    cfg.attrs    = &pattr;
    cfg.numAttrs = 1;

    cfg.gridDim = dim3(NGRAPH * ESPLIT, 1, 1);
    cudaLaunchKernelEx(&cfg, k_norm, edges);

    cfg.blockDim = dim3(128, 1, 1);
    cfg.gridDim  = dim3(GK * 8, 1, 1);
    cudaLaunchKernelEx(&cfg, gcn_gemm, embW, gw, gb);

    cfg.gridDim = dim3(B_TOTAL / RROWS, 1, 1);
    cudaLaunchKernelEx(&cfg, noise_main, gid, chain, td, tx, trigW, trigb,
                       embW, embb, out);
}

// round 15
// speedup vs baseline: 1.0029x; 1.0029x over previous
#include <cuda_runtime.h>
#include <cstdint>
#include <cstddef>

#define B_TOTAL 65536
#define NGRAPH  64
#define NNODES  2048
#define NEDGES  16384
#define META    64
#define TXD     8
#define NOISE   128
#define RROWS   32    // rows per block in main kernel
#define NFEAT   41
#define SPAD    36
#define ESPLIT  8
#define GK      128   // gcn_gemm K-splits
#define GROWS   16    // rows per gcn_gemm block

typedef unsigned long long ull;

// Scratch: [dinv | agg_part | g_go]
#define DINV_FLOATS (NGRAPH * NNODES)                   // 131072
#define PART_FLOATS (NGRAPH * ESPLIT * NNODES)          // 1048576
#define SCRATCH_FLOATS (DINV_FLOATS + PART_FLOATS + NGRAPH * NOISE)
__device__ float scratch[SCRATCH_FLOATS];
#define DINV     (scratch)
#define AGG_PART (scratch + DINV_FLOATS)
#define G_GO     (scratch + DINV_FLOATS + PART_FLOATS)

// ---------- PDL ----------
__device__ __forceinline__ void pdl_wait() {
    asm volatile("griddepcontrol.wait;" ::: "memory");
}

// ---------- f32x2 helpers ----------
__device__ __forceinline__ ull pack2(float lo, float hi) {
    ull r; asm("mov.b64 %0, {%1,%2};" : "=l"(r) : "f"(lo), "f"(hi)); return r;
}
__device__ __forceinline__ ull fma2(ull a, ull b, ull c) {
    ull d; asm("fma.rn.f32x2 %0, %1, %2, %3;" : "=l"(d) : "l"(a), "l"(b), "l"(c)); return d;
}
__device__ __forceinline__ void unpack2(ull v, float& lo, float& hi) {
    asm("mov.b64 {%0,%1}, %2;" : "=f"(lo), "=f"(hi) : "l"(v));
}
__device__ __forceinline__ void stcs4(float* p, float4 v) {
    asm volatile("st.global.cs.v4.f32 [%0], {%1,%2,%3,%4};"
                 :: "l"(p), "f"(v.x), "f"(v.y), "f"(v.z), "f"(v.w) : "memory");
}

// ============================================================================
// k_norm (chain HEAD, no wait): each block redundantly counts its graph's
// full 16K edge-destinations in smem (cheap), computes dinv, then
// smem-accumulates its split's norm contributions -> dense STG of agg_part.
// sp==0 blocks persist dinv and zero g_go. No k_deg kernel, no deg partials.
// 512 blocks = 64 graphs x 8 splits.
// ============================================================================
__global__ __launch_bounds__(256) void k_norm(const int* __restrict__ edges) {
    __shared__ float dinv_s[NNODES];
    __shared__ float agg_s[NNODES];
    const int g  = blockIdx.x >> 3;
    const int sp = blockIdx.x & 7;
    const int tid = threadIdx.x;

    const int* base = edges + (size_t)g * 2 * NEDGES;
    const int4* dall = reinterpret_cast<const int4*>(base + NEDGES);

    if (sp == 0 && tid < NOISE) G_GO[g * NOISE + tid] = 0.f;

    // count ALL destinations of this graph (redundant per split, but cheap)
    int* cnt = reinterpret_cast<int*>(dinv_s);
    #pragma unroll
    for (int i = 0; i < NNODES / 256; i++) cnt[i * 256 + tid] = 0;
    __syncthreads();
    #pragma unroll
    for (int i = 0; i < NEDGES / 4 / 256; i++) {
        int4 d = __ldg(&dall[i * 256 + tid]);
        atomicAdd(&cnt[d.x], 1);
        atomicAdd(&cnt[d.y], 1);
        atomicAdd(&cnt[d.z], 1);
        atomicAdd(&cnt[d.w], 1);
    }
    __syncthreads();
    #pragma unroll
    for (int i = 0; i < NNODES / 256; i++) {
        int n = i * 256 + tid;
        int c = cnt[n];
        dinv_s[n] = rsqrtf((float)c + 1.0f);   // +1 self loop
        agg_s[n]  = 0.f;
    }
    __syncthreads();

    // this split's edges
    const int4* src4 = reinterpret_cast<const int4*>(base) + sp * (NEDGES / ESPLIT / 4);
    const int4* dst4 = dall + sp * (NEDGES / ESPLIT / 4);
    int4 s0 = __ldg(&src4[tid]);
    int4 s1 = __ldg(&src4[256 + tid]);
    int4 d0 = __ldg(&dst4[tid]);
    int4 d1 = __ldg(&dst4[256 + tid]);

    atomicAdd(&agg_s[d0.x], dinv_s[s0.x] * dinv_s[d0.x]);
    atomicAdd(&agg_s[d0.y], dinv_s[s0.y] * dinv_s[d0.y]);
    atomicAdd(&agg_s[d0.z], dinv_s[s0.z] * dinv_s[d0.z]);
    atomicAdd(&agg_s[d0.w], dinv_s[s0.w] * dinv_s[d0.w]);
    atomicAdd(&agg_s[d1.x], dinv_s[s1.x] * dinv_s[d1.x]);
    atomicAdd(&agg_s[d1.y], dinv_s[s1.y] * dinv_s[d1.y]);
    atomicAdd(&agg_s[d1.z], dinv_s[s1.z] * dinv_s[d1.z]);
    atomicAdd(&agg_s[d1.w], dinv_s[s1.w] * dinv_s[d1.w]);
    __syncthreads();

    float* op = AGG_PART + (size_t)blockIdx.x * NNODES;
    #pragma unroll
    for (int i = 0; i < NNODES / 256; i++)
        op[i * 256 + tid] = agg_s[i * 256 + tid];

    if (sp == 0) {
        float* dv = DINV + (size_t)g * NNODES;
        #pragma unroll
        for (int i = 0; i < NNODES / 256; i++)
            dv[i * 256 + tid] = dinv_s[i * 256 + tid];
    }
}

// ============================================================================
// gcn_gemm: 1024 blocks = 128 K-splits (16 rows) x 8 graph-groups.
// Pass A (pre-wait): wsum. Wait. Sum agg partials + dinv^2 -> 16x8 FMA.
// g_go += w * ((AGG + dinv^2) @ embW_slice) + b * colsum(embW_slice)
// ============================================================================
__global__ __launch_bounds__(128) void gcn_gemm(
    const float* __restrict__ embW, const float* __restrict__ gwp,
    const float* __restrict__ gbp)
{
    __shared__ float aggs[8][GROWS];
    const int tid = threadIdx.x;
    const int ks  = blockIdx.x & (GK - 1);
    const int gsp = blockIdx.x >> 7;

    const float* wb = embW + (size_t)ks * GROWS * NOISE + tid;
    float wsum = 0.f;
    #pragma unroll
    for (int n = 0; n < GROWS; n++)
        wsum += __ldg(wb + (size_t)n * NOISE);

    pdl_wait();   // agg_part + dinv complete

    {
        int j = tid >> 4, n = tid & (GROWS - 1);
        int g = gsp * 8 + j;
        int node = ks * GROWS + n;
        float dv = __ldg(&DINV[(size_t)g * NNODES + node]);
        const float* ap = AGG_PART + (size_t)g * ESPLIT * NNODES + node;
        float asum = dv * dv;   // self-loop term
        #pragma unroll
        for (int sp = 0; sp < ESPLIT; sp++)
            asum += __ldg(&ap[sp * NNODES]);
        aggs[j][n] = asum;
    }
    __syncthreads();

    float acc[8] = {0.f, 0.f, 0.f, 0.f, 0.f, 0.f, 0.f, 0.f};
    #pragma unroll
    for (int n = 0; n < GROWS; n++) {
        float wv = __ldg(wb + (size_t)n * NOISE);
        #pragma unroll
        for (int j = 0; j < 8; j++)
            acc[j] = fmaf(aggs[j][n], wv, acc[j]);
    }
    const float w = gwp[0], b = gbp[0];
    const float bterm = b * wsum;
    #pragma unroll
    for (int j = 0; j < 8; j++)
        atomicAdd(&G_GO[(gsp * 8 + j) * NOISE + tid], fmaf(w, acc[j], bterm));
}

// ============================================================================
// noise_main (exact R12 config, 41.5us proven): staging + trig MLP PRE-wait;
// wait; g_go gather fused into acc init; f32x2 GEMM. 128 thr, 32 rows, occ 6.
// ============================================================================
__global__ __launch_bounds__(128, 6) void noise_main(
    const int*   __restrict__ gid,   const float* __restrict__ chain,
    const float* __restrict__ td,    const float* __restrict__ tx,
    const float* __restrict__ trigW, const float* __restrict__ trigb,
    const float* __restrict__ embW,  const float* __restrict__ embb,
    float* __restrict__ out)
{
    __shared__ __align__(16) float td_s[META][SPAD];
    __shared__ __align__(16) float feat_s[NFEAT][SPAD];
    __shared__ int gs[RROWS];

    const int tid = threadIdx.x;
    const int r0  = blockIdx.x * RROWS;
    const int lane = tid & 31;
    const int w    = tid >> 5;

    {
        const float4* tdg = reinterpret_cast<const float4*>(td + (size_t)r0 * META);
        #pragma unroll
        for (int it = 0; it < 4; it++) {
            int i = it * 128 + tid;
            int r = i >> 4;
            int q = i & 15;
            float4 v = tdg[i];
            float vv[4] = {v.x, v.y, v.z, v.w};
            #pragma unroll
            for (int j = 0; j < 4; j++) {
                int c = ((q >> 1) + j) & 3;
                td_s[4 * q + c][r] = vv[c];
            }
        }
        if (tid < 64) {
            const float4* txg = reinterpret_cast<const float4*>(tx + (size_t)r0 * TXD);
            int r = tid >> 1, q = tid & 1;
            float4 v = txg[tid];
            feat_s[33 + 4 * q + 0][r] = v.x;
            feat_s[33 + 4 * q + 1][r] = v.y;
            feat_s[33 + 4 * q + 2][r] = v.z;
            feat_s[33 + 4 * q + 3][r] = v.w;
        }
        if (tid < RROWS) {
            feat_s[0][tid] = chain[r0 + tid];
            gs[tid] = gid[r0 + tid];
        }
    }
    __syncthreads();

    {
        const int k = lane;
        float tb = __ldg(&trigb[k]);
        ull acc0 = pack2(tb, tb), acc1 = acc0, acc2 = acc0, acc3 = acc0;
        #pragma unroll 8
        for (int m = 0; m < META; m++) {
            float wv = __ldg(&trigW[m * 32 + k]);
            ull wd = pack2(wv, wv);
            ulonglong2 t01 = *reinterpret_cast<const ulonglong2*>(&td_s[m][8 * w]);
            ulonglong2 t23 = *reinterpret_cast<const ulonglong2*>(&td_s[m][8 * w + 4]);
            acc0 = fma2(wd, t01.x, acc0);
            acc1 = fma2(wd, t01.y, acc1);
            acc2 = fma2(wd, t23.x, acc2);
            acc3 = fma2(wd, t23.y, acc3);
        }
        float a, b2;
        unpack2(acc0, a, b2);
        *reinterpret_cast<ull*>(&feat_s[1 + k][8 * w + 0]) = pack2(fmaxf(a, 0.f), fmaxf(b2, 0.f));
        unpack2(acc1, a, b2);
        *reinterpret_cast<ull*>(&feat_s[1 + k][8 * w + 2]) = pack2(fmaxf(a, 0.f), fmaxf(b2, 0.f));
        unpack2(acc2, a, b2);
        *reinterpret_cast<ull*>(&feat_s[1 + k][8 * w + 4]) = pack2(fmaxf(a, 0.f), fmaxf(b2, 0.f));
        unpack2(acc3, a, b2);
        *reinterpret_cast<ull*>(&feat_s[1 + k][8 * w + 6]) = pack2(fmaxf(a, 0.f), fmaxf(b2, 0.f));
    }
    __syncthreads();

    pdl_wait();   // g_go complete

    {
        const int jq = lane;
        const float4 eb = __ldg(reinterpret_cast<const float4*>(&embb[4 * jq]));

        ull acc[4][4];
        #pragma unroll
        for (int u = 0; u < 4; u++) {
            int ra = 8 * w + 2 * u, rb = ra + 1;
            float4 ga = __ldg(reinterpret_cast<const float4*>(&G_GO[gs[ra] * NOISE + 4 * jq]));
            float4 gb = __ldg(reinterpret_cast<const float4*>(&G_GO[gs[rb] * NOISE + 4 * jq]));
            acc[u][0] = pack2(ga.x + eb.x, gb.x + eb.x);
            acc[u][1] = pack2(ga.y + eb.y, gb.y + eb.y);
            acc[u][2] = pack2(ga.z + eb.z, gb.z + eb.z);
            acc[u][3] = pack2(ga.w + eb.w, gb.w + eb.w);
        }

        const float4* wrow = reinterpret_cast<const float4*>(embW + (size_t)2048 * NOISE) + jq;
        #pragma unroll 4
        for (int k = 0; k < NFEAT; k++) {
            float4 wv = __ldg(wrow + (size_t)k * (NOISE / 4));
            ull wd0 = pack2(wv.x, wv.x);
            ull wd1 = pack2(wv.y, wv.y);
            ull wd2 = pack2(wv.z, wv.z);
            ull wd3 = pack2(wv.w, wv.w);
            ulonglong2 t01 = *reinterpret_cast<const ulonglong2*>(&feat_s[k][8 * w]);
            ulonglong2 t23 = *reinterpret_cast<const ulonglong2*>(&feat_s[k][8 * w + 4]);
            ull tp[4] = {t01.x, t01.y, t23.x, t23.y};
            #pragma unroll
            for (int u = 0; u < 4; u++) {
                acc[u][0] = fma2(wd0, tp[u], acc[u][0]);
                acc[u][1] = fma2(wd1, tp[u], acc[u][1]);
                acc[u][2] = fma2(wd2, tp[u], acc[u][2]);
                acc[u][3] = fma2(wd3, tp[u], acc[u][3]);
            }
        }

        #pragma unroll
        for (int u = 0; u < 4; u++) {
            size_t ra = (size_t)(r0 + 8 * w + 2 * u);
            float4 lo, hi;
            unpack2(acc[u][0], lo.x, hi.x);
            unpack2(acc[u][1], lo.y, hi.y);
            unpack2(acc[u][2], lo.z, hi.z);
            unpack2(acc[u][3], lo.w, hi.w);
            stcs4(out + ra * NOISE + 4 * jq, lo);
            stcs4(out + (ra + 1) * NOISE + 4 * jq, hi);
        }
    }
}

// ============================================================================
extern "C" void kernel_launch(void* const* d_in, const int* in_sizes, int n_in,
                              void* d_out, int out_size) {
    (void)in_sizes; (void)n_in; (void)out_size;
    const int*   gid   = (const int*)  d_in[0];
    const float* chain = (const float*)d_in[1];
    const float* td    = (const float*)d_in[2];
    const float* tx    = (const float*)d_in[3];
    const int*   edges = (const int*)  d_in[4];
    const float* gw    = (const float*)d_in[5];
    const float* gb    = (const float*)d_in[6];
    const float* trigW = (const float*)d_in[7];
    const float* trigb = (const float*)d_in[8];
    const float* embW  = (const float*)d_in[9];
    const float* embb  = (const float*)d_in[10];
    float* out = (float*)d_out;

    cudaLaunchAttribute pattr;
    pattr.id = cudaLaunchAttributeProgrammaticStreamSerialization;
    pattr.val.programmaticStreamSerializationAllowed = 1;

    // chain head: plain launch, no wait inside
    k_norm<<<NGRAPH * ESPLIT, 256>>>(edges);

    cudaLaunchConfig_t cfg = {};
    cfg.stream   = 0;
    cfg.attrs    = &pattr;
    cfg.numAttrs = 1;

    cfg.blockDim = dim3(128, 1, 1);
    cfg.gridDim  = dim3(GK * 8, 1, 1);
    cudaLaunchKernelEx(&cfg, gcn_gemm, embW, gw, gb);

    cfg.gridDim = dim3(B_TOTAL / RROWS, 1, 1);
    cudaLaunchKernelEx(&cfg, noise_main, gid, chain, td, tx, trigW, trigb,
                       embW, embb, out);
}

// round 16
// speedup vs baseline: 1.0126x; 1.0097x over previous
#include <cuda_runtime.h>
#include <cstdint>
#include <cstddef>

#define B_TOTAL 65536
#define NGRAPH  64
#define NNODES  2048
#define NEDGES  16384
#define META    64
#define TXD     8
#define NOISE   128
#define RROWS   32    // rows per block in main kernel
#define NFEAT   41
#define SPAD    36
#define ESPLIT  8
#define GK      128   // gcn_gemm K-splits
#define GROWS   16    // rows per gcn_gemm block

typedef unsigned long long ull;

// Scratch: [deg_part | agg_part | dinv | g_go]; partials are [g][sp][node]
#define PART_FLOATS (NGRAPH * ESPLIT * NNODES)          // 1048576
#define DINV_FLOATS (NGRAPH * NNODES)                   // 131072
#define SCRATCH_FLOATS (2 * PART_FLOATS + DINV_FLOATS + NGRAPH * NOISE)
__device__ float scratch[SCRATCH_FLOATS];
#define DEG_PART (scratch)
#define AGG_PART (scratch + PART_FLOATS)
#define DINV     (scratch + 2 * PART_FLOATS)
#define G_GO     (scratch + 2 * PART_FLOATS + DINV_FLOATS)

// ---------- PDL ----------
__device__ __forceinline__ void pdl_wait() {
    asm volatile("griddepcontrol.wait;" ::: "memory");
}

// ---------- f32x2 helpers ----------
__device__ __forceinline__ ull pack2(float lo, float hi) {
    ull r; asm("mov.b64 %0, {%1,%2};" : "=l"(r) : "f"(lo), "f"(hi)); return r;
}
__device__ __forceinline__ ull fma2(ull a, ull b, ull c) {
    ull d; asm("fma.rn.f32x2 %0, %1, %2, %3;" : "=l"(d) : "l"(a), "l"(b), "l"(c)); return d;
}
__device__ __forceinline__ void unpack2(ull v, float& lo, float& hi) {
    asm("mov.b64 {%0,%1}, %2;" : "=f"(lo), "=f"(hi) : "l"(v));
}
__device__ __forceinline__ void stcs4(float* p, float4 v) {
    asm volatile("st.global.cs.v4.f32 [%0], {%1,%2,%3,%4};"
                 :: "l"(p), "f"(v.x), "f"(v.y), "f"(v.z), "f"(v.w) : "memory");
}

// ============================================================================
// k_deg (chain head, no wait): per-split smem edge count -> dense STG of
// deg_part. Split-0 blocks also zero g_go (consumed 2 grids later).
// ============================================================================
__global__ __launch_bounds__(256) void k_deg(const int* __restrict__ edges) {
    __shared__ int cnt[NNODES];
    const int g  = blockIdx.x >> 3;
    const int sp = blockIdx.x & 7;
    const int tid = threadIdx.x;

    const int4* dst4 = reinterpret_cast<const int4*>(
        edges + (size_t)g * 2 * NEDGES + NEDGES) + sp * (NEDGES / ESPLIT / 4);
    int4 d0 = __ldg(&dst4[tid]);
    int4 d1 = __ldg(&dst4[256 + tid]);

    if (sp == 0 && tid < NOISE) G_GO[g * NOISE + tid] = 0.f;

    #pragma unroll
    for (int i = 0; i < NNODES / 256; i++) cnt[i * 256 + tid] = 0;
    __syncthreads();

    atomicAdd(&cnt[d0.x], 1);
    atomicAdd(&cnt[d0.y], 1);
    atomicAdd(&cnt[d0.z], 1);
    atomicAdd(&cnt[d0.w], 1);
    atomicAdd(&cnt[d1.x], 1);
    atomicAdd(&cnt[d1.y], 1);
    atomicAdd(&cnt[d1.z], 1);
    atomicAdd(&cnt[d1.w], 1);
    __syncthreads();

    float* op = DEG_PART + (size_t)blockIdx.x * NNODES;
    #pragma unroll
    for (int i = 0; i < NNODES / 256; i++)
        op[i * 256 + tid] = (float)cnt[i * 256 + tid];
}

// ============================================================================
// k_norm: edge loads (prologue) -> wait -> sum deg partials -> dinv in smem ->
// smem-accumulate split's norm contributions -> dense STG of agg_part.
// sp==0 blocks also persist dinv (shortens gcn_gemm's post-wait tail).
// ============================================================================
__global__ __launch_bounds__(256) void k_norm(const int* __restrict__ edges) {
    __shared__ float dinv_s[NNODES];
    __shared__ float agg_s[NNODES];
    const int g  = blockIdx.x >> 3;
    const int sp = blockIdx.x & 7;
    const int tid = threadIdx.x;

    const int* base = edges + (size_t)g * 2 * NEDGES;
    const int4* src4 = reinterpret_cast<const int4*>(base) + sp * (NEDGES / ESPLIT / 4);
    const int4* dst4 = reinterpret_cast<const int4*>(base + NEDGES) + sp * (NEDGES / ESPLIT / 4);
    int4 s0 = __ldg(&src4[tid]);
    int4 s1 = __ldg(&src4[256 + tid]);
    int4 d0 = __ldg(&dst4[tid]);
    int4 d1 = __ldg(&dst4[256 + tid]);

    pdl_wait();   // deg_part complete

    const float* dp = DEG_PART + (size_t)g * ESPLIT * NNODES;
    #pragma unroll
    for (int i = 0; i < NNODES / 256; i++) {
        int n = i * 256 + tid;
        float s = 1.0f;   // self loop
        #pragma unroll
        for (int spp = 0; spp < ESPLIT; spp++)
            s += __ldg(&dp[spp * NNODES + n]);
        dinv_s[n] = rsqrtf(s);
        agg_s[n]  = 0.f;
    }
    __syncthreads();

    atomicAdd(&agg_s[d0.x], dinv_s[s0.x] * dinv_s[d0.x]);
    atomicAdd(&agg_s[d0.y], dinv_s[s0.y] * dinv_s[d0.y]);
    atomicAdd(&agg_s[d0.z], dinv_s[s0.z] * dinv_s[d0.z]);
    atomicAdd(&agg_s[d0.w], dinv_s[s0.w] * dinv_s[d0.w]);
    atomicAdd(&agg_s[d1.x], dinv_s[s1.x] * dinv_s[d1.x]);
    atomicAdd(&agg_s[d1.y], dinv_s[s1.y] * dinv_s[d1.y]);
    atomicAdd(&agg_s[d1.z], dinv_s[s1.z] * dinv_s[d1.z]);
    atomicAdd(&agg_s[d1.w], dinv_s[s1.w] * dinv_s[d1.w]);
    __syncthreads();

    float* op = AGG_PART + (size_t)blockIdx.x * NNODES;
    #pragma unroll
    for (int i = 0; i < NNODES / 256; i++)
        op[i * 256 + tid] = agg_s[i * 256 + tid];

    if (sp == 0) {
        float* dv = DINV + (size_t)g * NNODES;
        #pragma unroll
        for (int i = 0; i < NNODES / 256; i++)
            dv[i * 256 + tid] = dinv_s[i * 256 + tid];
    }
}

// ============================================================================
// gcn_gemm: 1024 blocks = 128 K-splits (16 rows) x 8 graph-groups.
// Pass A (pre-wait): wsum. Wait. dinv load + 8 agg partials -> 16x8 FMA.
// g_go += w * ((AGG + dinv^2) @ embW_slice) + b * colsum(embW_slice)
// ============================================================================
__global__ __launch_bounds__(128) void gcn_gemm(
    const float* __restrict__ embW, const float* __restrict__ gwp,
    const float* __restrict__ gbp)
{
    __shared__ float aggs[8][GROWS];
    const int tid = threadIdx.x;
    const int ks  = blockIdx.x & (GK - 1);
    const int gsp = blockIdx.x >> 7;

    const float* wb = embW + (size_t)ks * GROWS * NOISE + tid;
    float wsum = 0.f;
    #pragma unroll
    for (int n = 0; n < GROWS; n++)
        wsum += __ldg(wb + (size_t)n * NOISE);

    pdl_wait();   // agg_part + dinv complete

    {
        int j = tid >> 4, n = tid & (GROWS - 1);
        int g = gsp * 8 + j;
        int node = ks * GROWS + n;
        float dv = __ldg(&DINV[(size_t)g * NNODES + node]);
        const float* ap = AGG_PART + (size_t)g * ESPLIT * NNODES + node;
        float asum = dv * dv;   // self-loop term
        #pragma unroll
        for (int sp = 0; sp < ESPLIT; sp++)
            asum += __ldg(&ap[sp * NNODES]);
        aggs[j][n] = asum;
    }
    __syncthreads();

    float acc[8] = {0.f, 0.f, 0.f, 0.f, 0.f, 0.f, 0.f, 0.f};
    #pragma unroll
    for (int n = 0; n < GROWS; n++) {
        float wv = __ldg(wb + (size_t)n * NOISE);
        #pragma unroll
        for (int j = 0; j < 8; j++)
            acc[j] = fmaf(aggs[j][n], wv, acc[j]);
    }
    const float w = gwp[0], b = gbp[0];
    const float bterm = b * wsum;
    #pragma unroll
    for (int j = 0; j < 8; j++)
        atomicAdd(&G_GO[(gsp * 8 + j) * NOISE + tid], fmaf(w, acc[j], bterm));
}

// ============================================================================
// noise_main (exact R12 config, 41.5us proven): staging + trig MLP PRE-wait;
// wait; g_go gather fused into acc init; f32x2 GEMM. 128 thr, 32 rows, occ 6.
// ============================================================================
__global__ __launch_bounds__(128, 6) void noise_main(
    const int*   __restrict__ gid,   const float* __restrict__ chain,
    const float* __restrict__ td,    const float* __restrict__ tx,
    const float* __restrict__ trigW, const float* __restrict__ trigb,
    const float* __restrict__ embW,  const float* __restrict__ embb,
    float* __restrict__ out)
{
    __shared__ __align__(16) float td_s[META][SPAD];
    __shared__ __align__(16) float feat_s[NFEAT][SPAD];
    __shared__ int gs[RROWS];

    const int tid = threadIdx.x;
    const int r0  = blockIdx.x * RROWS;
    const int lane = tid & 31;
    const int w    = tid >> 5;

    {
        const float4* tdg = reinterpret_cast<const float4*>(td + (size_t)r0 * META);
        #pragma unroll
        for (int it = 0; it < 4; it++) {
            int i = it * 128 + tid;
            int r = i >> 4;
            int q = i & 15;
            float4 v = tdg[i];
            float vv[4] = {v.x, v.y, v.z, v.w};
            #pragma unroll
            for (int j = 0; j < 4; j++) {
                int c = ((q >> 1) + j) & 3;
                td_s[4 * q + c][r] = vv[c];
            }
        }
        if (tid < 64) {
            const float4* txg = reinterpret_cast<const float4*>(tx + (size_t)r0 * TXD);
            int r = tid >> 1, q = tid & 1;
            float4 v = txg[tid];
            feat_s[33 + 4 * q + 0][r] = v.x;
            feat_s[33 + 4 * q + 1][r] = v.y;
            feat_s[33 + 4 * q + 2][r] = v.z;
            feat_s[33 + 4 * q + 3][r] = v.w;
        }
        if (tid < RROWS) {
            feat_s[0][tid] = chain[r0 + tid];
            gs[tid] = gid[r0 + tid];
        }
    }
    __syncthreads();

    {
        const int k = lane;
        float tb = __ldg(&trigb[k]);
        ull acc0 = pack2(tb, tb), acc1 = acc0, acc2 = acc0, acc3 = acc0;
        #pragma unroll 8
        for (int m = 0; m < META; m++) {
            float wv = __ldg(&trigW[m * 32 + k]);
            ull wd = pack2(wv, wv);
            ulonglong2 t01 = *reinterpret_cast<const ulonglong2*>(&td_s[m][8 * w]);
            ulonglong2 t23 = *reinterpret_cast<const ulonglong2*>(&td_s[m][8 * w + 4]);
            acc0 = fma2(wd, t01.x, acc0);
            acc1 = fma2(wd, t01.y, acc1);
            acc2 = fma2(wd, t23.x, acc2);
            acc3 = fma2(wd, t23.y, acc3);
        }
        float a, b2;
        unpack2(acc0, a, b2);
        *reinterpret_cast<ull*>(&feat_s[1 + k][8 * w + 0]) = pack2(fmaxf(a, 0.f), fmaxf(b2, 0.f));
        unpack2(acc1, a, b2);
        *reinterpret_cast<ull*>(&feat_s[1 + k][8 * w + 2]) = pack2(fmaxf(a, 0.f), fmaxf(b2, 0.f));
        unpack2(acc2, a, b2);
        *reinterpret_cast<ull*>(&feat_s[1 + k][8 * w + 4]) = pack2(fmaxf(a, 0.f), fmaxf(b2, 0.f));
        unpack2(acc3, a, b2);
        *reinterpret_cast<ull*>(&feat_s[1 + k][8 * w + 6]) = pack2(fmaxf(a, 0.f), fmaxf(b2, 0.f));
    }
    __syncthreads();

    pdl_wait();   // g_go complete

    {
        const int jq = lane;
        const float4 eb = __ldg(reinterpret_cast<const float4*>(&embb[4 * jq]));

        ull acc[4][4];
        #pragma unroll
        for (int u = 0; u < 4; u++) {
            int ra = 8 * w + 2 * u, rb = ra + 1;
            float4 ga = __ldg(reinterpret_cast<const float4*>(&G_GO[gs[ra] * NOISE + 4 * jq]));
            float4 gb = __ldg(reinterpret_cast<const float4*>(&G_GO[gs[rb] * NOISE + 4 * jq]));
            acc[u][0] = pack2(ga.x + eb.x, gb.x + eb.x);
            acc[u][1] = pack2(ga.y + eb.y, gb.y + eb.y);
            acc[u][2] = pack2(ga.z + eb.z, gb.z + eb.z);
            acc[u][3] = pack2(ga.w + eb.w, gb.w + eb.w);
        }

        const float4* wrow = reinterpret_cast<const float4*>(embW + (size_t)2048 * NOISE) + jq;
        #pragma unroll 4
        for (int k = 0; k < NFEAT; k++) {
            float4 wv = __ldg(wrow + (size_t)k * (NOISE / 4));
            ull wd0 = pack2(wv.x, wv.x);
            ull wd1 = pack2(wv.y, wv.y);
            ull wd2 = pack2(wv.z, wv.z);
            ull wd3 = pack2(wv.w, wv.w);
            ulonglong2 t01 = *reinterpret_cast<const ulonglong2*>(&feat_s[k][8 * w]);
            ulonglong2 t23 = *reinterpret_cast<const ulonglong2*>(&feat_s[k][8 * w + 4]);
            ull tp[4] = {t01.x, t01.y, t23.x, t23.y};
            #pragma unroll
            for (int u = 0; u < 4; u++) {
                acc[u][0] = fma2(wd0, tp[u], acc[u][0]);
                acc[u][1] = fma2(wd1, tp[u], acc[u][1]);
                acc[u][2] = fma2(wd2, tp[u], acc[u][2]);
                acc[u][3] = fma2(wd3, tp[u], acc[u][3]);
            }
        }

        #pragma unroll
        for (int u = 0; u < 4; u++) {
            size_t ra = (size_t)(r0 + 8 * w + 2 * u);
            float4 lo, hi;
            unpack2(acc[u][0], lo.x, hi.x);
            unpack2(acc[u][1], lo.y, hi.y);
            unpack2(acc[u][2], lo.z, hi.z);
            unpack2(acc[u][3], lo.w, hi.w);
            stcs4(out + ra * NOISE + 4 * jq, lo);
            stcs4(out + (ra + 1) * NOISE + 4 * jq, hi);
        }
    }
}

// ============================================================================
extern "C" void kernel_launch(void* const* d_in, const int* in_sizes, int n_in,
                              void* d_out, int out_size) {
    (void)in_sizes; (void)n_in; (void)out_size;
    const int*   gid   = (const int*)  d_in[0];
    const float* chain = (const float*)d_in[1];
    const float* td    = (const float*)d_in[2];
    const float* tx    = (const float*)d_in[3];
    const int*   edges = (const int*)  d_in[4];
    const float* gw    = (const float*)d_in[5];
    const float* gb    = (const float*)d_in[6];
    const float* trigW = (const float*)d_in[7];
    const float* trigb = (const float*)d_in[8];
    const float* embW  = (const float*)d_in[9];
    const float* embb  = (const float*)d_in[10];
    float* out = (float*)d_out;

    cudaLaunchAttribute pattr;
    pattr.id = cudaLaunchAttributeProgrammaticStreamSerialization;
    pattr.val.programmaticStreamSerializationAllowed = 1;

    // chain head: plain launch, no wait inside
    k_deg<<<NGRAPH * ESPLIT, 256>>>(edges);

    cudaLaunchConfig_t cfg = {};
    cfg.stream   = 0;
    cfg.attrs    = &pattr;
    cfg.numAttrs = 1;

    cfg.blockDim = dim3(256, 1, 1);
    cfg.gridDim  = dim3(NGRAPH * ESPLIT, 1, 1);
    cudaLaunchKernelEx(&cfg, k_norm, edges);

    cfg.blockDim = dim3(128, 1, 1);
    cfg.gridDim  = dim3(GK * 8, 1, 1);
    cudaLaunchKernelEx(&cfg, gcn_gemm, embW, gw, gb);

    cfg.gridDim = dim3(B_TOTAL / RROWS, 1, 1);
    cudaLaunchKernelEx(&cfg, noise_main, gid, chain, td, tx, trigW, trigb,
                       embW, embb, out);
}